// round 9
// baseline (speedup 1.0000x reference)
#include <cuda_runtime.h>
#include <stdint.h>
#include <math.h>

// Problem constants
#define Bdim 16
#define Nn   1024
#define Dd   256
#define Mm   128
#define Cc   8192
#define NEG_SLOPE 0.2f
#define LOG2E 1.442695041f

#define BND (Bdim * Nn * Dd)                 // 4,194,304 (per modality)
#define ND  (Nn * Dd)                        // per-batch stride
#define NN2 (Nn * Nn)

#define GEMM_SMEM 98304                      // 3 stages x 32KB

// ---------------- scratch (device globals; no allocation) ----------------
__device__ float g_xp[3 * BND];              // projected inputs
__device__ float g_h [3 * BND];              // hypergraph outputs (tf32-rounded)
__device__ float g_Q [3 * BND];              // rounded-x staging
__device__ float g_pack[3L * Bdim * Nn * 1024];  // packed [Q|K|V|O] projections
__device__ float g_pb[1024];                 // packed bias
__device__ float g_VT[3 * BND];              // V transposed per (mod,batch), tf32-rounded
__device__ float g_WT[5 * Dd * Dd];          // W_hg,WQ,WK,WV,WO transposed+rounded
__device__ float g_S6[6L * Bdim * Nn * Nn];  // raw attention scores, all 6 pairs
__device__ float g_off[6 * Bdim * Nn];       // per-row softmax offset (log2 domain)
__device__ float g_msg[6L * BND];            // per-pair PV outputs
__device__ float g_es[3 * Mm * Bdim * Dd];
__device__ float g_xe[3 * Mm * Bdim * Dd];
__device__ float g_e [3 * Cc * Bdim];
__device__ float g_p1[3 * Bdim * Nn];        // dot(xp, att1)
__device__ float g_p2[3 * Mm * Bdim];        // dot(es, att2)
__device__ int   g_ncnt[3 * Nn], g_noff[3 * Nn], g_nlist[3 * Cc];
__device__ int   g_ecnt[3 * Mm], g_eoff[3 * Mm], g_elist[3 * Cc];

// ---------------- helpers -------------------------------------------------
__device__ __forceinline__ uint32_t smem_u32(const void* p) {
    uint32_t a;
    asm("{ .reg .u64 t; cvta.to.shared.u64 t, %1; cvt.u32.u64 %0, t; }"
        : "=r"(a) : "l"(p));
    return a;
}
__device__ __forceinline__ uint32_t swz128(uint32_t off) {
    return off ^ ((off >> 3) & 0x70);
}
__device__ __forceinline__ uint32_t rna_u(float x) {
    uint32_t r;
    asm("cvt.rna.tf32.f32 %0, %1;" : "=r"(r) : "f"(x));
    return r;
}
__device__ __forceinline__ float rna_f(float x) { return __uint_as_float(rna_u(x)); }
__device__ __forceinline__ float ex2f(float x) {
    float r; asm("ex2.approx.f32 %0, %1;" : "=f"(r) : "f"(x)); return r;
}
__device__ __forceinline__ float lg2f(float x) {
    float r; asm("lg2.approx.f32 %0, %1;" : "=f"(r) : "f"(x)); return r;
}

__device__ __forceinline__ void ldsm4(uint32_t* r, uint32_t addr) {
    asm volatile("ldmatrix.sync.aligned.m8n8.x4.shared.b16 {%0,%1,%2,%3}, [%4];"
        : "=r"(r[0]), "=r"(r[1]), "=r"(r[2]), "=r"(r[3]) : "r"(addr));
}
__device__ __forceinline__ void mma8(float* c, const uint32_t* a, const uint32_t* b) {
    asm volatile(
        "mma.sync.aligned.m16n8k8.row.col.f32.tf32.tf32.f32 "
        "{%0,%1,%2,%3}, {%4,%5,%6,%7}, {%8,%9}, {%0,%1,%2,%3};"
        : "+f"(c[0]), "+f"(c[1]), "+f"(c[2]), "+f"(c[3])
        : "r"(a[0]), "r"(a[1]), "r"(a[2]), "r"(a[3]), "r"(b[0]), "r"(b[1]));
}
__device__ __forceinline__ void cpasync16(uint32_t s, const void* g) {
    asm volatile("cp.async.cg.shared.global [%0], [%1], 16;" :: "r"(s), "l"(g));
}
__device__ __forceinline__ void cpcommit() {
    asm volatile("cp.async.commit_group;" ::: "memory");
}
template<int N>
__device__ __forceinline__ void cpwait() {
    asm volatile("cp.async.wait_group %0;" :: "n"(N) : "memory");
}

// ---------------- tf32 mma GEMM body (BK=32, 3-stage cp.async) -----------
// C[128,128]@(i0,j0) = alpha * A[.,K] @ B^T (+bias) (+C).
// A row-major [rows x Kext] pitch pitchA; B row-major [N x Kext] pitch pitchB.
// FE: A elements transformed p = rna(exp2(fma(a, LOG2E, off[row]))) while
// staging G->S (softmax applied on the fly); A path uses LDG+STS, B cp.async.
template<bool FE>
__device__ __forceinline__ void gemm_body(
    const float* __restrict__ A, const float* __restrict__ Bg,
    const float* __restrict__ bias, float* __restrict__ Cg,
    int Ncols, int pitchC, int Kext, int pitchA, int pitchB,
    int i0, int j0, float alpha, int accum, int rndC,
    const float* __restrict__ offs)
{
    extern __shared__ float smem[];

    const int tid = threadIdx.x, lane = tid & 31, wid = tid >> 5;
    const int wm = (wid & 1) * 64, wn = (wid >> 1) * 32;

    float acc[4][4][4];
#pragma unroll
    for (int i = 0; i < 4; i++)
#pragma unroll
        for (int j = 0; j < 4; j++)
#pragma unroll
            for (int c = 0; c < 4; c++) acc[i][j][c] = 0.f;

    const uint32_t base = smem_u32(smem);
    const uint32_t aoff = (uint32_t)((wm + (lane & 7) + (lane & 8)) * 128
                                     + ((lane >> 4) & 1) * 16);
    const uint32_t boff = (uint32_t)((wn + (lane & 7) + ((lane >> 4) & 1) * 8) * 128
                                     + ((lane >> 3) & 1) * 16);

    const int lr = tid >> 3, lkq = tid & 7;      // 32 rows/step, 8 quads/row
    uint32_t so[4];
#pragma unroll
    for (int q = 0; q < 4; q++)
        so[q] = swz128((lr + q * 32) * 128 + lkq * 16);
    const float* aG = A + (long)(i0 + lr) * pitchA + lkq * 4;
    const float* bG = Bg + (long)(j0 + lr) * pitchB + lkq * 4;
    const int nkt = Kext >> 5;

    auto issueB = [&](int kt) {
        const uint32_t sb = base + (uint32_t)(kt % 3) * 32768 + 16384;
        const long k0 = (long)(kt << 5);
#pragma unroll
        for (int q = 0; q < 4; q++)
            cpasync16(sb + so[q], bG + (long)(q * 32) * pitchB + k0);
        cpcommit();
    };
    auto issueAB = [&](int kt) {
        const uint32_t sb = base + (uint32_t)(kt % 3) * 32768;
        const long k0 = (long)(kt << 5);
#pragma unroll
        for (int q = 0; q < 4; q++)
            cpasync16(sb + so[q], aG + (long)(q * 32) * pitchA + k0);
#pragma unroll
        for (int q = 0; q < 4; q++)
            cpasync16(sb + 16384 + so[q], bG + (long)(q * 32) * pitchB + k0);
        cpcommit();
    };

    float offR[4];
    float4 ar[4];
    auto ldgA = [&](int kt) {
        const long k0 = (long)(kt << 5);
#pragma unroll
        for (int q = 0; q < 4; q++)
            ar[q] = *(const float4*)(aG + (long)(q * 32) * pitchA + k0);
    };
    auto stsA = [&](int kt) {
        const uint32_t sb = base + (uint32_t)(kt % 3) * 32768;
#pragma unroll
        for (int q = 0; q < 4; q++) {
            float4 v = ar[q];
            float o = offR[q];
            v.x = rna_f(ex2f(fmaf(v.x, LOG2E, o)));
            v.y = rna_f(ex2f(fmaf(v.y, LOG2E, o)));
            v.z = rna_f(ex2f(fmaf(v.z, LOG2E, o)));
            v.w = rna_f(ex2f(fmaf(v.w, LOG2E, o)));
            *(float4*)((char*)smem + (sb - base) + so[q]) = v;
        }
    };

    if (FE) {
#pragma unroll
        for (int q = 0; q < 4; q++) offR[q] = offs[i0 + lr + q * 32];
        ldgA(0);
        stsA(0);
        issueB(0);
        issueB(1);
    } else {
        issueAB(0);
        issueAB(1);
    }
    cpwait<1>();
    __syncthreads();

    for (int kt = 0; kt < nkt; kt++) {
        const uint32_t stb = base + (uint32_t)(kt % 3) * 32768;
        if (FE) {
            if (kt + 1 < nkt) ldgA(kt + 1);
            if (kt + 2 < nkt) issueB(kt + 2);
        } else {
            if (kt + 2 < nkt) issueAB(kt + 2);
        }

        const uint32_t sa = stb, sb = stb + 16384;
#pragma unroll
        for (int s = 0; s < 4; s++) {
            uint32_t af[4][4], bf[4][2];
#pragma unroll
            for (int mt = 0; mt < 4; mt++)
                ldsm4(af[mt], sa + swz128(aoff + mt * 2048 + s * 32));
#pragma unroll
            for (int p = 0; p < 2; p++) {
                uint32_t r[4];
                ldsm4(r, sb + swz128(boff + p * 2048 + s * 32));
                bf[2 * p][0] = r[0]; bf[2 * p][1] = r[1];
                bf[2 * p + 1][0] = r[2]; bf[2 * p + 1][1] = r[3];
            }
#pragma unroll
            for (int mt = 0; mt < 4; mt++)
#pragma unroll
                for (int nt = 0; nt < 4; nt++)
                    mma8(acc[mt][nt], af[mt], bf[nt]);
        }

        if (kt + 1 < nkt) {
            if (FE) stsA(kt + 1);
            if (kt + 2 < nkt) cpwait<1>(); else cpwait<0>();
            __syncthreads();
        }
    }

    // epilogue
#pragma unroll
    for (int mt = 0; mt < 4; mt++) {
        int row = i0 + wm + mt * 16 + (lane >> 2);
#pragma unroll
        for (int nt = 0; nt < 4; nt++) {
            int col = j0 + wn + nt * 8 + (lane & 3) * 2;
            float bb0 = 0.f, bb1 = 0.f;
            if (bias) { bb0 = bias[col]; bb1 = bias[col + 1]; }
            long p0 = (long)row * pitchC + col;
            long p1 = (long)(row + 8) * pitchC + col;
            float v0 = acc[mt][nt][0] * alpha + bb0;
            float v1 = acc[mt][nt][1] * alpha + bb1;
            float v2 = acc[mt][nt][2] * alpha + bb0;
            float v3 = acc[mt][nt][3] * alpha + bb1;
            if (accum) {
                float2 c0 = *(float2*)&Cg[p0];
                float2 c1 = *(float2*)&Cg[p1];
                v0 += c0.x; v1 += c0.y; v2 += c1.x; v3 += c1.y;
            }
            if (rndC) { v0 = rna_f(v0); v1 = rna_f(v1); v2 = rna_f(v2); v3 = rna_f(v3); }
            *(float2*)&Cg[p0] = make_float2(v0, v1);
            *(float2*)&Cg[p1] = make_float2(v2, v3);
        }
    }
}

// generic strided wrapper (plain path)
__global__ __launch_bounds__(256, 2)
void gemm_lin(const float* __restrict__ A, const float* __restrict__ Bg,
              const float* __restrict__ bias, float* __restrict__ Cg,
              int Ncols, int pitchC, int Kext, int pitchA, int pitchB,
              long sA, long sB, long sC, float alpha, int accum, int rndC)
{
    gemm_body<false>(A + (long)blockIdx.z * sA, Bg + (long)blockIdx.z * sB, bias,
                     Cg + (long)blockIdx.z * sC, Ncols, pitchC, Kext, pitchA, pitchB,
                     blockIdx.y * 128, blockIdx.x * 128, alpha, accum, rndC, nullptr);
}

// ---------------- QK^T strip-persistent with fused online row stats ------
// Each CTA: one (pair,batch), 128 Q rows, loops all 8 column tiles.
// Writes raw scaled S and the per-row softmax offset (log2 domain).
__global__ __launch_bounds__(256, 2)
void gemm_qk_stats(const float* __restrict__ pack, float* __restrict__ S6,
                   float* __restrict__ offv)
{
    extern __shared__ float smem[];
    __shared__ float redbuf[128 * 4];
    __shared__ float mrun[128], lrun[128], mnewbuf[128];

    int z = blockIdx.z, p = z >> 4, b = z & 15, m = p >> 1, j = p & 1;
    int n = j + (j >= m);
    const float* Qp = pack + ((long)m * (Bdim * Nn) + b * Nn) * 1024;
    const float* Kp = pack + ((long)n * (Bdim * Nn) + b * Nn) * 1024 + 256;
    float* S = S6 + ((long)p * 16 + b) * NN2;
    float* offp = offv + ((long)p * 16 + b) * Nn;

    const int tid = threadIdx.x, lane = tid & 31, wid = tid >> 5;
    const int wm = (wid & 1) * 64, wn = (wid >> 1) * 32;
    const int i0 = blockIdx.x * 128;

    if (tid < 128) { mrun[tid] = -3e38f; lrun[tid] = 0.f; }

    const uint32_t base = smem_u32(smem);
    const uint32_t aoff = (uint32_t)((wm + (lane & 7) + (lane & 8)) * 128
                                     + ((lane >> 4) & 1) * 16);
    const uint32_t boff = (uint32_t)((wn + (lane & 7) + ((lane >> 4) & 1) * 8) * 128
                                     + ((lane >> 3) & 1) * 16);
    const int lr = tid >> 3, lkq = tid & 7;
    uint32_t so[4];
#pragma unroll
    for (int q = 0; q < 4; q++)
        so[q] = swz128((lr + q * 32) * 128 + lkq * 16);
    const float* aG = Qp + (long)(i0 + lr) * 1024 + lkq * 4;

    for (int jt = 0; jt < 8; jt++) {
        const float* bG = Kp + (long)(jt * 128 + lr) * 1024 + lkq * 4;

        float acc[4][4][4];
#pragma unroll
        for (int i = 0; i < 4; i++)
#pragma unroll
            for (int jj = 0; jj < 4; jj++)
#pragma unroll
                for (int c = 0; c < 4; c++) acc[i][jj][c] = 0.f;

        auto issueAB = [&](int kt) {
            const uint32_t sb = base + (uint32_t)(kt % 3) * 32768;
            const long k0 = (long)(kt << 5);
#pragma unroll
            for (int q = 0; q < 4; q++)
                cpasync16(sb + so[q], aG + (long)(q * 32) * 1024 + k0);
#pragma unroll
            for (int q = 0; q < 4; q++)
                cpasync16(sb + 16384 + so[q], bG + (long)(q * 32) * 1024 + k0);
            cpcommit();
        };

        issueAB(0);
        issueAB(1);
        cpwait<1>();
        __syncthreads();

        const int nkt = 8;     // K = 256
        for (int kt = 0; kt < nkt; kt++) {
            const uint32_t stb = base + (uint32_t)(kt % 3) * 32768;
            if (kt + 2 < nkt) issueAB(kt + 2);
            const uint32_t sa = stb, sb = stb + 16384;
#pragma unroll
            for (int s = 0; s < 4; s++) {
                uint32_t af[4][4], bf[4][2];
#pragma unroll
                for (int mt = 0; mt < 4; mt++)
                    ldsm4(af[mt], sa + swz128(aoff + mt * 2048 + s * 32));
#pragma unroll
                for (int pp = 0; pp < 2; pp++) {
                    uint32_t r[4];
                    ldsm4(r, sb + swz128(boff + pp * 2048 + s * 32));
                    bf[2 * pp][0] = r[0]; bf[2 * pp][1] = r[1];
                    bf[2 * pp + 1][0] = r[2]; bf[2 * pp + 1][1] = r[3];
                }
#pragma unroll
                for (int mt = 0; mt < 4; mt++)
#pragma unroll
                    for (int nt = 0; nt < 4; nt++)
                        mma8(acc[mt][nt], af[mt], bf[nt]);
            }
            if (kt + 1 < nkt) {
                if (kt + 2 < nkt) cpwait<1>(); else cpwait<0>();
                __syncthreads();
            }
        }

        // scale + write raw S tile
#pragma unroll
        for (int mt = 0; mt < 4; mt++) {
            int row = i0 + wm + mt * 16 + (lane >> 2);
#pragma unroll
            for (int nt = 0; nt < 4; nt++) {
                int col = jt * 128 + wn + nt * 8 + (lane & 3) * 2;
                acc[mt][nt][0] *= 0.0625f; acc[mt][nt][1] *= 0.0625f;
                acc[mt][nt][2] *= 0.0625f; acc[mt][nt][3] *= 0.0625f;
                *(float2*)&S[(long)row * Nn + col] =
                    make_float2(acc[mt][nt][0], acc[mt][nt][1]);
                *(float2*)&S[(long)(row + 8) * Nn + col] =
                    make_float2(acc[mt][nt][2], acc[mt][nt][3]);
            }
        }

        // online stats: tile row max
        __syncthreads();
#pragma unroll
        for (int mt = 0; mt < 4; mt++) {
#pragma unroll
            for (int h = 0; h < 2; h++) {
                float v = -3e38f;
#pragma unroll
                for (int nt = 0; nt < 4; nt++)
                    v = fmaxf(v, fmaxf(acc[mt][nt][2 * h], acc[mt][nt][2 * h + 1]));
                v = fmaxf(v, __shfl_xor_sync(0xffffffffu, v, 1));
                v = fmaxf(v, __shfl_xor_sync(0xffffffffu, v, 2));
                if ((lane & 3) == 0)
                    redbuf[(wm + mt * 16 + (lane >> 2) + h * 8) * 4 + (wid >> 1)] = v;
            }
        }
        __syncthreads();
        if (tid < 128) {
            float tm = fmaxf(fmaxf(redbuf[tid * 4], redbuf[tid * 4 + 1]),
                             fmaxf(redbuf[tid * 4 + 2], redbuf[tid * 4 + 3]));
            mnewbuf[tid] = fmaxf(mrun[tid], tm);
        }
        __syncthreads();
        // tile row sum of exp relative to new max
#pragma unroll
        for (int mt = 0; mt < 4; mt++) {
#pragma unroll
            for (int h = 0; h < 2; h++) {
                int row = wm + mt * 16 + (lane >> 2) + h * 8;
                float mn = mnewbuf[row];
                float s = 0.f;
#pragma unroll
                for (int nt = 0; nt < 4; nt++)
                    s += ex2f((acc[mt][nt][2 * h] - mn) * LOG2E)
                       + ex2f((acc[mt][nt][2 * h + 1] - mn) * LOG2E);
                s += __shfl_xor_sync(0xffffffffu, s, 1);
                s += __shfl_xor_sync(0xffffffffu, s, 2);
                if ((lane & 3) == 0)
                    redbuf[row * 4 + (wid >> 1)] = s;
            }
        }
        __syncthreads();
        if (tid < 128) {
            float mn = mnewbuf[tid];
            lrun[tid] = lrun[tid] * ex2f((mrun[tid] - mn) * LOG2E)
                      + (redbuf[tid * 4] + redbuf[tid * 4 + 1]
                       + redbuf[tid * 4 + 2] + redbuf[tid * 4 + 3]);
            mrun[tid] = mn;
        }
    }

    if (tid < 128)
        offp[i0 + tid] = -(mrun[tid] * LOG2E + lg2f(lrun[tid]));
}

// PV for all 6 pairs with fused softmax (exp applied in A staging path)
__global__ __launch_bounds__(256)
void gemm_pv(const float* __restrict__ S6, const float* __restrict__ off,
             const float* __restrict__ VT, float* __restrict__ msg)
{
    int z = blockIdx.z, p = z >> 4, b = z & 15, m = p >> 1, j = p & 1;
    int n = j + (j >= m);
    gemm_body<true>(S6 + ((long)p * 16 + b) * NN2,
                    VT + (long)n * BND + (long)b * ND, nullptr,
                    msg + (long)p * BND + (long)b * ND,
                    Dd, Dd, Nn, 1024, 1024,
                    blockIdx.y * 128, blockIdx.x * 128, 1.f, 0, 0,
                    off + ((long)p * 16 + b) * Nn);
}

// ---------------- pre-round x to tf32 ------------------------------------
__global__ void round3_kernel(const float* __restrict__ a, const float* __restrict__ b,
                              const float* __restrict__ c, float* __restrict__ dst)
{
    long i = (long)blockIdx.x * blockDim.x + threadIdx.x;
    long stride = (long)gridDim.x * blockDim.x;
    for (; i < BND; i += stride) {
        dst[i]            = rna_f(a[i]);
        dst[BND + i]      = rna_f(b[i]);
        dst[2L * BND + i] = rna_f(c[i]);
    }
}

// ---------------- transpose (dst[C][R] = src[R][C]), tf32-rounded ---------
__global__ void transpose_kernel(const float* __restrict__ src, float* __restrict__ dst,
                                 int R, int C, int srcPitch, long sS, long sD)
{
    __shared__ float t[32][33];
    src += (long)blockIdx.z * sS;
    dst += (long)blockIdx.z * sD;
    int c = blockIdx.x * 32 + threadIdx.x;
    int r0 = blockIdx.y * 32;
    for (int j = threadIdx.y; j < 32; j += 8)
        t[j][threadIdx.x] = src[(long)(r0 + j) * srcPitch + c];
    __syncthreads();
    int rr = blockIdx.y * 32 + threadIdx.x;
    int cc0 = blockIdx.x * 32;
    for (int j = threadIdx.y; j < 32; j += 8)
        dst[(long)(cc0 + j) * R + rr] = rna_f(t[threadIdx.x][j]);
}

// 5 weight transposes in one launch (z selects matrix)
__global__ void transpose_w5(const float* w0, const float* w1, const float* w2,
                             const float* w3, const float* w4, float* __restrict__ dst)
{
    __shared__ float t[32][33];
    const float* src = (blockIdx.z == 0) ? w0 : (blockIdx.z == 1) ? w1 :
                       (blockIdx.z == 2) ? w2 : (blockIdx.z == 3) ? w3 : w4;
    dst += (long)blockIdx.z * Dd * Dd;
    int c = blockIdx.x * 32 + threadIdx.x;
    int r0 = blockIdx.y * 32;
    for (int j = threadIdx.y; j < 32; j += 8)
        t[j][threadIdx.x] = src[(long)(r0 + j) * Dd + c];
    __syncthreads();
    int rr = blockIdx.y * 32 + threadIdx.x;
    int cc0 = blockIdx.x * 32;
    for (int j = threadIdx.y; j < 32; j += 8)
        dst[(long)(cc0 + j) * Dd + rr] = rna_f(t[threadIdx.x][j]);
}

// packed bias [bQ|bK|bV|bO]
__global__ void pack_bias(const float* q, const float* k, const float* v,
                          const float* o, float* __restrict__ pb)
{
    int i = blockIdx.x * 256 + threadIdx.x;
    const float* s = (i < 256) ? q : (i < 512) ? k : (i < 768) ? v : o;
    pb[i] = s[i & 255];
}

// ---------------- fast deterministic CSR build ----------------------------
__global__ void zero_cnt_kernel(int* ncnt, int* ecnt)
{
    int i = blockIdx.x * blockDim.x + threadIdx.x;
    if (i < 3 * Nn) ncnt[i] = 0;
    if (i < 3 * Mm) ecnt[i] = 0;
}

__global__ void csr_count_kernel(const int* __restrict__ i0, const int* __restrict__ i1,
                                 const int* __restrict__ i2, int cnt_stride, int edge_off,
                                 int* __restrict__ cnt)
{
    const int* idx = (blockIdx.y == 0) ? i0 : (blockIdx.y == 1) ? i1 : i2;
    int c = blockIdx.x * blockDim.x + threadIdx.x;
    atomicAdd(&cnt[blockIdx.y * cnt_stride + idx[edge_off + c]], 1);
}

__global__ void csr_scan_kernel(const int* __restrict__ cnt, int* __restrict__ off, int nseg)
{
    __shared__ int buf[1024];
    int tid = threadIdx.x;
    int v = (tid < nseg) ? cnt[blockIdx.x * nseg + tid] : 0;
    buf[tid] = v;
    __syncthreads();
    for (int o = 1; o < nseg; o <<= 1) {
        int t = (tid >= o) ? buf[tid - o] : 0;
        __syncthreads();
        buf[tid] += t;
        __syncthreads();
    }
    if (tid < nseg) off[blockIdx.x * nseg + tid] = buf[tid] - v;
}

__global__ void csr_fill_kernel(const int* __restrict__ i0, const int* __restrict__ i1,
                                const int* __restrict__ i2, int nseg, int edge_off,
                                const int* __restrict__ off, int* __restrict__ list)
{
    __shared__ int sidx[Cc];
    const int* idx = (blockIdx.y == 0) ? i0 : (blockIdx.y == 1) ? i1 : i2;
    int tid = threadIdx.x;
    for (int i = tid; i < Cc; i += blockDim.x) sidx[i] = idx[edge_off + i];
    __syncthreads();

    int w = tid >> 5, lane = tid & 31;
    int s = blockIdx.x * 8 + w;
    if (s >= nseg) return;
    int p = off[blockIdx.y * nseg + s];
    int* lst = list + blockIdx.y * Cc;
    for (int c0 = 0; c0 < Cc; c0 += 32) {
        int c = c0 + lane;
        bool m = (sidx[c] == s);
        unsigned bal = __ballot_sync(0xffffffffu, m);
        if (m) lst[p + __popc(bal & ((1u << lane) - 1u))] = c;
        p += __popc(bal);
    }
}

// ---------------- sparse stage kernels (z = modality) ---------------------
__global__ void edge_sum_kernel(const float* __restrict__ xp,
                                const int* __restrict__ h0, const int* __restrict__ h1,
                                const int* __restrict__ h2,
                                const int* __restrict__ ecnt, const int* __restrict__ eoff,
                                const int* __restrict__ elist, float* __restrict__ es)
{
    int mmod = blockIdx.z;
    const int* hidx = (mmod == 0) ? h0 : (mmod == 1) ? h1 : h2;
    xp += (long)mmod * BND;
    es += (long)mmod * Mm * Bdim * Dd;
    ecnt += mmod * Mm; eoff += mmod * Mm; elist += mmod * Cc;

    int e = blockIdx.x, b = blockIdx.y, d = threadIdx.x;
    int cnt = ecnt[e], off = eoff[e];
    float s = 0.f;
    for (int i = 0; i < cnt; i++) {
        int c = elist[off + i];
        int node = hidx[c];
        s += xp[((long)b * Nn + node) * Dd + d];
    }
    es[((long)e * Bdim + b) * Dd + d] = s;
}

// proj: p1[mod][row] = dot(xp[row,:], att[0:D]); p2 for es rows
__global__ void proj_kernel(const float* __restrict__ xp, const float* __restrict__ es,
                            const float* __restrict__ att,
                            float* __restrict__ p1, float* __restrict__ p2)
{
    int mmod = blockIdx.y;
    int row = blockIdx.x * 8 + (threadIdx.x >> 5);
    int lane = threadIdx.x & 31;
    const float* src;
    const float* a;
    if (row < Bdim * Nn) {
        src = xp + (long)mmod * BND + (long)row * Dd;
        a = att;
    } else {
        src = es + (long)mmod * Mm * Bdim * Dd + (long)(row - Bdim * Nn) * Dd;
        a = att + Dd;
    }
    float s = 0.f;
#pragma unroll
    for (int i = 0; i < Dd / 32; i++) {
        int d = lane + 32 * i;
        s += src[d] * a[d];
    }
#pragma unroll
    for (int o = 16; o; o >>= 1) s += __shfl_xor_sync(0xffffffffu, s, o);
    if (lane == 0) {
        if (row < Bdim * Nn) p1[mmod * Bdim * Nn + row] = s;
        else                 p2[mmod * Mm * Bdim + row - Bdim * Nn] = s;
    }
}

__global__ void logits_gather(const int* __restrict__ h0, const int* __restrict__ h1,
                              const int* __restrict__ h2,
                              const float* __restrict__ p1, const float* __restrict__ p2,
                              float* __restrict__ e_out)
{
    int mmod = blockIdx.y;
    const int* hidx = (mmod == 0) ? h0 : (mmod == 1) ? h1 : h2;
    int i = blockIdx.x * blockDim.x + threadIdx.x;
    int c = i >> 4, b = i & 15;
    float v = p1[mmod * Bdim * Nn + b * Nn + hidx[c]]
            + p2[mmod * Mm * Bdim + hidx[Cc + c] * Bdim + b];
    e_out[(long)mmod * Cc * Bdim + i] = (v >= 0.f) ? v : NEG_SLOPE * v;
}

__global__ void node_softmax(float* __restrict__ e, const int* __restrict__ ncnt,
                             const int* __restrict__ noff, const int* __restrict__ nlist)
{
    int mmod = blockIdx.y;
    e += (long)mmod * Cc * Bdim;
    ncnt += mmod * Nn; noff += mmod * Nn; nlist += mmod * Cc;

    int n = blockIdx.x, b = threadIdx.x;
    if (b >= Bdim) return;
    int cnt = ncnt[n];
    if (!cnt) return;
    int off = noff[n];
    float mx = -1e30f;
    for (int i = 0; i < cnt; i++) {
        int c = nlist[off + i];
        mx = fmaxf(mx, e[c * Bdim + b]);
    }
    float sum = 0.f;
    for (int i = 0; i < cnt; i++) {
        int c = nlist[off + i];
        float v = expf(e[c * Bdim + b] - mx);
        e[c * Bdim + b] = v;
        sum += v;
    }
    float inv = 1.f / (sum + 1e-16f);
    for (int i = 0; i < cnt; i++) {
        int c = nlist[off + i];
        e[c * Bdim + b] *= inv;
    }
}

__global__ void xedge_kernel(const float* __restrict__ xp, const float* __restrict__ alpha,
                             const int* __restrict__ h0, const int* __restrict__ h1,
                             const int* __restrict__ h2,
                             const int* __restrict__ ecnt, const int* __restrict__ eoff,
                             const int* __restrict__ elist, float* __restrict__ xe)
{
    int mmod = blockIdx.z;
    const int* hidx = (mmod == 0) ? h0 : (mmod == 1) ? h1 : h2;
    xp += (long)mmod * BND;
    alpha += (long)mmod * Cc * Bdim;
    xe += (long)mmod * Mm * Bdim * Dd;
    ecnt += mmod * Mm; eoff += mmod * Mm; elist += mmod * Cc;

    int e = blockIdx.x, b = blockIdx.y, d = threadIdx.x;
    int cnt = ecnt[e];
    float s = 0.f;
    if (cnt) {
        int off = eoff[e];
        for (int i = 0; i < cnt; i++) {
            int c = elist[off + i];
            int node = hidx[c];
            s += alpha[c * Bdim + b] * xp[((long)b * Nn + node) * Dd + d];
        }
        s /= (float)cnt;
    }
    xe[((long)e * Bdim + b) * Dd + d] = s;
}

__global__ void xnode_kernel(const float* __restrict__ xe, const float* __restrict__ alpha,
                             const int* __restrict__ h0, const int* __restrict__ h1,
                             const int* __restrict__ h2,
                             const int* __restrict__ ncnt, const int* __restrict__ noff,
                             const int* __restrict__ nlist, float* __restrict__ h)
{
    int mmod = blockIdx.z;
    const int* hidx = (mmod == 0) ? h0 : (mmod == 1) ? h1 : h2;
    xe += (long)mmod * Mm * Bdim * Dd;
    alpha += (long)mmod * Cc * Bdim;
    h += (long)mmod * BND;
    ncnt += mmod * Nn; noff += mmod * Nn; nlist += mmod * Cc;

    int n = blockIdx.x, b = blockIdx.y, d = threadIdx.x;
    int cnt = ncnt[n];
    float s = 0.f;
    if (cnt) {
        int off = noff[n];
        for (int i = 0; i < cnt; i++) {
            int c = nlist[off + i];
            int eidx = hidx[Cc + c];
            s += alpha[c * Bdim + b] * xe[((long)eidx * Bdim + b) * Dd + d];
        }
        s /= (float)cnt;
    }
    h[((long)b * Nn + n) * Dd + d] = rna_f(s);
}

// ---------------- out = relu(base(pack col 768+) + msg0 + msg1) -----------
__global__ void relu_final(float* __restrict__ out, const float* __restrict__ pack,
                           const float* __restrict__ msg)
{
    long i = (long)blockIdx.x * blockDim.x + threadIdx.x;
    long stride = (long)gridDim.x * blockDim.x;
    for (; i < BND; i += stride) {
        long r = i >> 8;
        int d = (int)(i & 255);
#pragma unroll
        for (int m = 0; m < 3; m++) {
            float v = pack[((long)m * (Bdim * Nn) + r) * 1024 + 768 + d]
                    + msg[(long)(2 * m) * BND + i]
                    + msg[(long)(2 * m + 1) * BND + i];
            out[(long)m * BND + i] = fmaxf(v, 0.f);
        }
    }
}

// ---------------- launcher -------------------------------------------------
extern "C" void kernel_launch(void* const* d_in, const int* in_sizes, int n_in,
                              void* d_out, int out_size)
{
    const float* x[3]    = {(const float*)d_in[0], (const float*)d_in[1], (const float*)d_in[2]};
    const int*   hidx[3] = {(const int*)d_in[3], (const int*)d_in[4], (const int*)d_in[5]};
    const float* W_hg = (const float*)d_in[6];
    const float* att  = (const float*)d_in[7];
    const float* WQ = (const float*)d_in[8];
    const float* bQ = (const float*)d_in[9];
    const float* WK = (const float*)d_in[10];
    const float* bK = (const float*)d_in[11];
    const float* WV = (const float*)d_in[12];
    const float* bV = (const float*)d_in[13];
    const float* WO = (const float*)d_in[14];
    const float* bO = (const float*)d_in[15];
    float* out = (float*)d_out;

    static int smem_set = 0;
    if (!smem_set) {
        cudaFuncSetAttribute(gemm_lin, cudaFuncAttributeMaxDynamicSharedMemorySize, GEMM_SMEM);
        cudaFuncSetAttribute(gemm_qk_stats, cudaFuncAttributeMaxDynamicSharedMemorySize, GEMM_SMEM);
        cudaFuncSetAttribute(gemm_pv,  cudaFuncAttributeMaxDynamicSharedMemorySize, GEMM_SMEM);
        smem_set = 1;
    }

    float *xp, *h, *Q, *pack, *pb, *VT, *WT, *S6, *offb, *msg, *es, *xe, *ealpha, *p1, *p2;
    int *ncnt, *noff, *nlist, *ecnt, *eoff, *elist;
    cudaGetSymbolAddress((void**)&xp, g_xp);
    cudaGetSymbolAddress((void**)&h,  g_h);
    cudaGetSymbolAddress((void**)&Q,  g_Q);
    cudaGetSymbolAddress((void**)&pack, g_pack);
    cudaGetSymbolAddress((void**)&pb, g_pb);
    cudaGetSymbolAddress((void**)&VT, g_VT);
    cudaGetSymbolAddress((void**)&WT, g_WT);
    cudaGetSymbolAddress((void**)&S6, g_S6);
    cudaGetSymbolAddress((void**)&offb, g_off);
    cudaGetSymbolAddress((void**)&msg, g_msg);
    cudaGetSymbolAddress((void**)&es, g_es);
    cudaGetSymbolAddress((void**)&xe, g_xe);
    cudaGetSymbolAddress((void**)&ealpha, g_e);
    cudaGetSymbolAddress((void**)&p1, g_p1);
    cudaGetSymbolAddress((void**)&p2, g_p2);
    cudaGetSymbolAddress((void**)&ncnt, g_ncnt);
    cudaGetSymbolAddress((void**)&noff, g_noff);
    cudaGetSymbolAddress((void**)&nlist, g_nlist);
    cudaGetSymbolAddress((void**)&ecnt, g_ecnt);
    cudaGetSymbolAddress((void**)&eoff, g_eoff);
    cudaGetSymbolAddress((void**)&elist, g_elist);

    const int DD = Dd * Dd;

    // 0) weight transposes (tf32-rounded) + pre-round x + packed bias
    transpose_w5<<<dim3(8, 8, 5), dim3(32, 8)>>>(W_hg, WQ, WK, WV, WO, WT);
    round3_kernel<<<4096, 256>>>(x[0], x[1], x[2], Q);
    pack_bias<<<4, 256>>>(bQ, bK, bV, bO, pb);

    // 1) xp = x @ W_hg, all 3 modalities
    gemm_lin<<<dim3(2, 128, 3), 256, GEMM_SMEM>>>(Q, WT, nullptr, xp,
                                                  Dd, Dd, Dd, Dd, Dd,
                                                  BND, 0, BND, 1.f, 0, 0);

    // 2) CSR build (parallel, deterministic: lists sorted by c)
    zero_cnt_kernel<<<4, 1024>>>(ncnt, ecnt);
    csr_count_kernel<<<dim3(Cc / 256, 3), 256>>>(hidx[0], hidx[1], hidx[2], Nn, 0,  ncnt);
    csr_count_kernel<<<dim3(Cc / 256, 3), 256>>>(hidx[0], hidx[1], hidx[2], Mm, Cc, ecnt);
    csr_scan_kernel<<<3, 1024>>>(ncnt, noff, Nn);
    csr_scan_kernel<<<3, 1024>>>(ecnt, eoff, Mm);
    csr_fill_kernel<<<dim3(Nn / 8, 3), 256>>>(hidx[0], hidx[1], hidx[2], Nn, 0,  noff, nlist);
    csr_fill_kernel<<<dim3(Mm / 8, 3), 256>>>(hidx[0], hidx[1], hidx[2], Mm, Cc, eoff, elist);

    // 3-7) sparse hypergraph pipeline
    edge_sum_kernel<<<dim3(Mm, Bdim, 3), Dd>>>(xp, hidx[0], hidx[1], hidx[2],
                                               ecnt, eoff, elist, es);
    proj_kernel<<<dim3((Bdim * Nn + Mm * Bdim) / 8, 3), 256>>>(xp, es, att, p1, p2);
    logits_gather<<<dim3(Cc * Bdim / 256, 3), 256>>>(hidx[0], hidx[1], hidx[2],
                                                     p1, p2, ealpha);
    node_softmax<<<dim3(Nn, 3), 32>>>(ealpha, ncnt, noff, nlist);
    xedge_kernel<<<dim3(Mm, Bdim, 3), Dd>>>(xp, ealpha, hidx[0], hidx[1], hidx[2],
                                            ecnt, eoff, elist, xe);
    xnode_kernel<<<dim3(Nn, Bdim, 3), Dd>>>(xe, ealpha, hidx[0], hidx[1], hidx[2],
                                            ncnt, noff, nlist, h);

    // 8) fused Q|K|V|O projections: [49152,256] @ [256,1024] -> packed
    gemm_lin<<<dim3(8, 384, 1), 256, GEMM_SMEM>>>(h, WT + DD, pb, pack,
                                                  1024, 1024, Dd, Dd, Dd,
                                                  0, 0, 0, 1.f, 0, 1);

    // 8b) VT[z][d][n] from pack V columns (pitch 1024), tf32-rounded
    transpose_kernel<<<dim3(Dd / 32, Nn / 32, 48), dim3(32, 8)>>>(
        pack + 512, VT, Nn, Dd, 1024, (long)Nn * 1024, ND);

    // 9) cross-modal attention: strip-persistent QK^T with fused row stats,
    //    then PV with fused softmax
    gemm_qk_stats<<<dim3(8, 1, 96), 256, GEMM_SMEM>>>(pack, S6, offb);
    gemm_pv<<<dim3(2, 8, 96), 256, GEMM_SMEM>>>(S6, offb, VT, msg);

    // 10) final combine + relu
    relu_final<<<4096, 256>>>(out, pack, msg);
}

// round 12
// speedup vs baseline: 1.0564x; 1.0564x over previous
#include <cuda_runtime.h>
#include <stdint.h>
#include <math.h>

// Problem constants
#define Bdim 16
#define Nn   1024
#define Dd   256
#define Mm   128
#define Cc   8192
#define NEG_SLOPE 0.2f
#define LOG2E 1.442695041f

#define BND (Bdim * Nn * Dd)                 // 4,194,304 (per modality)
#define ND  (Nn * Dd)                        // per-batch stride
#define NN2 (Nn * Nn)

#define GEMM_SMEM 98304                      // 3 stages x 32KB

// ---------------- scratch (device globals; no allocation) ----------------
__device__ float g_xp[3 * BND];              // projected inputs
__device__ float g_h [3 * BND];              // hypergraph outputs (tf32-rounded)
__device__ float g_Q [3 * BND];              // rounded-x staging
__device__ float g_pack[3L * Bdim * Nn * 1024];  // packed [Q|K|V|O] projections
__device__ float g_pb[1024];                 // packed bias
__device__ float g_VT[3 * BND];              // V transposed per (mod,batch), tf32-rounded
__device__ float g_WT[5 * Dd * Dd];          // W_hg,WQ,WK,WV,WO transposed+rounded
__device__ float g_S6[6L * Bdim * Nn * Nn];  // raw attention scores, all 6 pairs
__device__ float g_off[6 * Bdim * Nn];       // per-row softmax offset (log2 domain)
__device__ float g_pm[6L * Bdim * Nn * 8];   // per-(row, coltile) max partials
__device__ float g_pl[6L * Bdim * Nn * 8];   // per-(row, coltile) sumexp partials
__device__ float g_msg[6L * BND];            // per-pair PV outputs
__device__ float g_es[3 * Mm * Bdim * Dd];
__device__ float g_xe[3 * Mm * Bdim * Dd];
__device__ float g_e [3 * Cc * Bdim];
__device__ float g_p1[3 * Bdim * Nn];        // dot(xp, att1)
__device__ float g_p2[3 * Mm * Bdim];        // dot(es, att2)
__device__ int   g_ncnt[3 * Nn], g_noff[3 * Nn], g_nlist[3 * Cc];
__device__ int   g_ecnt[3 * Mm], g_eoff[3 * Mm], g_elist[3 * Cc];

// ---------------- helpers -------------------------------------------------
__device__ __forceinline__ uint32_t smem_u32(const void* p) {
    uint32_t a;
    asm("{ .reg .u64 t; cvta.to.shared.u64 t, %1; cvt.u32.u64 %0, t; }"
        : "=r"(a) : "l"(p));
    return a;
}
__device__ __forceinline__ uint32_t swz128(uint32_t off) {
    return off ^ ((off >> 3) & 0x70);
}
__device__ __forceinline__ uint32_t rna_u(float x) {
    uint32_t r;
    asm("cvt.rna.tf32.f32 %0, %1;" : "=r"(r) : "f"(x));
    return r;
}
__device__ __forceinline__ float rna_f(float x) { return __uint_as_float(rna_u(x)); }
__device__ __forceinline__ float ex2f(float x) {
    float r; asm("ex2.approx.f32 %0, %1;" : "=f"(r) : "f"(x)); return r;
}
__device__ __forceinline__ float lg2f(float x) {
    float r; asm("lg2.approx.f32 %0, %1;" : "=f"(r) : "f"(x)); return r;
}

__device__ __forceinline__ void ldsm4(uint32_t* r, uint32_t addr) {
    asm volatile("ldmatrix.sync.aligned.m8n8.x4.shared.b16 {%0,%1,%2,%3}, [%4];"
        : "=r"(r[0]), "=r"(r[1]), "=r"(r[2]), "=r"(r[3]) : "r"(addr));
}
__device__ __forceinline__ void mma8(float* c, const uint32_t* a, const uint32_t* b) {
    asm volatile(
        "mma.sync.aligned.m16n8k8.row.col.f32.tf32.tf32.f32 "
        "{%0,%1,%2,%3}, {%4,%5,%6,%7}, {%8,%9}, {%0,%1,%2,%3};"
        : "+f"(c[0]), "+f"(c[1]), "+f"(c[2]), "+f"(c[3])
        : "r"(a[0]), "r"(a[1]), "r"(a[2]), "r"(a[3]), "r"(b[0]), "r"(b[1]));
}
__device__ __forceinline__ void cpasync16(uint32_t s, const void* g) {
    asm volatile("cp.async.cg.shared.global [%0], [%1], 16;" :: "r"(s), "l"(g));
}
__device__ __forceinline__ void cpcommit() {
    asm volatile("cp.async.commit_group;" ::: "memory");
}
template<int N>
__device__ __forceinline__ void cpwait() {
    asm volatile("cp.async.wait_group %0;" :: "n"(N) : "memory");
}

// ---------------- tf32 mma GEMM body (BK=32, 3-stage cp.async) -----------
// C[128,128]@(i0,j0) = alpha * A[.,K] @ B^T (+bias) (+C).
// A row-major [rows x Kext] pitch pitchA; B row-major [N x Kext] pitch pitchB.
// FE: A elements transformed p = rna(exp2(fma(a, LOG2E, off[row]))) while
// staging G->S (softmax applied on the fly); A path uses LDG+STS, B cp.async.
template<bool FE>
__device__ __forceinline__ void gemm_body(
    const float* __restrict__ A, const float* __restrict__ Bg,
    const float* __restrict__ bias, float* __restrict__ Cg,
    int Ncols, int pitchC, int Kext, int pitchA, int pitchB,
    int i0, int j0, float alpha, int accum, int rndC,
    const float* __restrict__ offs)
{
    extern __shared__ float smem[];

    const int tid = threadIdx.x, lane = tid & 31, wid = tid >> 5;
    const int wm = (wid & 1) * 64, wn = (wid >> 1) * 32;

    float acc[4][4][4];
#pragma unroll
    for (int i = 0; i < 4; i++)
#pragma unroll
        for (int j = 0; j < 4; j++)
#pragma unroll
            for (int c = 0; c < 4; c++) acc[i][j][c] = 0.f;

    const uint32_t base = smem_u32(smem);
    const uint32_t aoff = (uint32_t)((wm + (lane & 7) + (lane & 8)) * 128
                                     + ((lane >> 4) & 1) * 16);
    const uint32_t boff = (uint32_t)((wn + (lane & 7) + ((lane >> 4) & 1) * 8) * 128
                                     + ((lane >> 3) & 1) * 16);

    const int lr = tid >> 3, lkq = tid & 7;      // 32 rows/step, 8 quads/row
    uint32_t so[4];
#pragma unroll
    for (int q = 0; q < 4; q++)
        so[q] = swz128((lr + q * 32) * 128 + lkq * 16);
    const float* aG = A + (long)(i0 + lr) * pitchA + lkq * 4;
    const float* bG = Bg + (long)(j0 + lr) * pitchB + lkq * 4;
    const int nkt = Kext >> 5;

    auto issueB = [&](int kt) {
        const uint32_t sb = base + (uint32_t)(kt % 3) * 32768 + 16384;
        const long k0 = (long)(kt << 5);
#pragma unroll
        for (int q = 0; q < 4; q++)
            cpasync16(sb + so[q], bG + (long)(q * 32) * pitchB + k0);
        cpcommit();
    };
    auto issueAB = [&](int kt) {
        const uint32_t sb = base + (uint32_t)(kt % 3) * 32768;
        const long k0 = (long)(kt << 5);
#pragma unroll
        for (int q = 0; q < 4; q++)
            cpasync16(sb + so[q], aG + (long)(q * 32) * pitchA + k0);
#pragma unroll
        for (int q = 0; q < 4; q++)
            cpasync16(sb + 16384 + so[q], bG + (long)(q * 32) * pitchB + k0);
        cpcommit();
    };

    float offR[4];
    float4 ar[4];
    auto ldgA = [&](int kt) {
        const long k0 = (long)(kt << 5);
#pragma unroll
        for (int q = 0; q < 4; q++)
            ar[q] = *(const float4*)(aG + (long)(q * 32) * pitchA + k0);
    };
    auto stsA = [&](int kt) {
        const uint32_t sb = base + (uint32_t)(kt % 3) * 32768;
#pragma unroll
        for (int q = 0; q < 4; q++) {
            float4 v = ar[q];
            float o = offR[q];
            v.x = rna_f(ex2f(fmaf(v.x, LOG2E, o)));
            v.y = rna_f(ex2f(fmaf(v.y, LOG2E, o)));
            v.z = rna_f(ex2f(fmaf(v.z, LOG2E, o)));
            v.w = rna_f(ex2f(fmaf(v.w, LOG2E, o)));
            *(float4*)((char*)smem + (sb - base) + so[q]) = v;
        }
    };

    if (FE) {
#pragma unroll
        for (int q = 0; q < 4; q++) offR[q] = offs[i0 + lr + q * 32];
        ldgA(0);
        stsA(0);
        issueB(0);
        issueB(1);
    } else {
        issueAB(0);
        issueAB(1);
    }
    cpwait<1>();
    __syncthreads();

    for (int kt = 0; kt < nkt; kt++) {
        const uint32_t stb = base + (uint32_t)(kt % 3) * 32768;
        if (FE) {
            if (kt + 1 < nkt) ldgA(kt + 1);
            if (kt + 2 < nkt) issueB(kt + 2);
        } else {
            if (kt + 2 < nkt) issueAB(kt + 2);
        }

        const uint32_t sa = stb, sb = stb + 16384;
#pragma unroll
        for (int s = 0; s < 4; s++) {
            uint32_t af[4][4], bf[4][2];
#pragma unroll
            for (int mt = 0; mt < 4; mt++)
                ldsm4(af[mt], sa + swz128(aoff + mt * 2048 + s * 32));
#pragma unroll
            for (int p = 0; p < 2; p++) {
                uint32_t r[4];
                ldsm4(r, sb + swz128(boff + p * 2048 + s * 32));
                bf[2 * p][0] = r[0]; bf[2 * p][1] = r[1];
                bf[2 * p + 1][0] = r[2]; bf[2 * p + 1][1] = r[3];
            }
#pragma unroll
            for (int mt = 0; mt < 4; mt++)
#pragma unroll
                for (int nt = 0; nt < 4; nt++)
                    mma8(acc[mt][nt], af[mt], bf[nt]);
        }

        if (kt + 1 < nkt) {
            if (FE) stsA(kt + 1);
            if (kt + 2 < nkt) cpwait<1>(); else cpwait<0>();
            __syncthreads();
        }
    }

    // epilogue
#pragma unroll
    for (int mt = 0; mt < 4; mt++) {
        int row = i0 + wm + mt * 16 + (lane >> 2);
#pragma unroll
        for (int nt = 0; nt < 4; nt++) {
            int col = j0 + wn + nt * 8 + (lane & 3) * 2;
            float bb0 = 0.f, bb1 = 0.f;
            if (bias) { bb0 = bias[col]; bb1 = bias[col + 1]; }
            long p0 = (long)row * pitchC + col;
            long p1 = (long)(row + 8) * pitchC + col;
            float v0 = acc[mt][nt][0] * alpha + bb0;
            float v1 = acc[mt][nt][1] * alpha + bb1;
            float v2 = acc[mt][nt][2] * alpha + bb0;
            float v3 = acc[mt][nt][3] * alpha + bb1;
            if (accum) {
                float2 c0 = *(float2*)&Cg[p0];
                float2 c1 = *(float2*)&Cg[p1];
                v0 += c0.x; v1 += c0.y; v2 += c1.x; v3 += c1.y;
            }
            if (rndC) { v0 = rna_f(v0); v1 = rna_f(v1); v2 = rna_f(v2); v3 = rna_f(v3); }
            *(float2*)&Cg[p0] = make_float2(v0, v1);
            *(float2*)&Cg[p1] = make_float2(v2, v3);
        }
    }
}

// generic strided wrapper (plain path)
__global__ __launch_bounds__(256, 2)
void gemm_lin(const float* __restrict__ A, const float* __restrict__ Bg,
              const float* __restrict__ bias, float* __restrict__ Cg,
              int Ncols, int pitchC, int Kext, int pitchA, int pitchB,
              long sA, long sB, long sC, float alpha, int accum, int rndC)
{
    gemm_body<false>(A + (long)blockIdx.z * sA, Bg + (long)blockIdx.z * sB, bias,
                     Cg + (long)blockIdx.z * sC, Ncols, pitchC, Kext, pitchA, pitchB,
                     blockIdx.y * 128, blockIdx.x * 128, alpha, accum, rndC, nullptr);
}

// ---------------- QK^T with per-CTA stats partials ------------------------
// Same tiled shape as R8's gemm_qk (grid x=col tile, y=row tile, z=pair*16+b).
// After writing the scaled S tile, reduces per-row tile-max / tile-sumexp and
// writes them to pm/pl[row*8 + jt] for the combine kernel.
__global__ __launch_bounds__(256, 2)
void gemm_qk_part(const float* __restrict__ pack, float* __restrict__ S6,
                  float* __restrict__ pm, float* __restrict__ pl)
{
    extern __shared__ float smem[];
    __shared__ float redbuf[128 * 4];
    __shared__ float mbuf[128];

    const int z = blockIdx.z, p = z >> 4, b = z & 15, m = p >> 1, jsel = p & 1;
    const int n = jsel + (jsel >= m);
    const float* Qp = pack + ((long)m * (Bdim * Nn) + b * Nn) * 1024;
    const float* Kp = pack + ((long)n * (Bdim * Nn) + b * Nn) * 1024 + 256;
    float* S = S6 + ((long)z) * NN2;

    const int tid = threadIdx.x, lane = tid & 31, wid = tid >> 5;
    const int wm = (wid & 1) * 64, wn = (wid >> 1) * 32;
    const int i0 = blockIdx.y * 128, jt = blockIdx.x;
    const int j0 = jt * 128;

    float acc[4][4][4];
#pragma unroll
    for (int i = 0; i < 4; i++)
#pragma unroll
        for (int jj = 0; jj < 4; jj++)
#pragma unroll
            for (int c = 0; c < 4; c++) acc[i][jj][c] = 0.f;

    const uint32_t base = smem_u32(smem);
    const uint32_t aoff = (uint32_t)((wm + (lane & 7) + (lane & 8)) * 128
                                     + ((lane >> 4) & 1) * 16);
    const uint32_t boff = (uint32_t)((wn + (lane & 7) + ((lane >> 4) & 1) * 8) * 128
                                     + ((lane >> 3) & 1) * 16);
    const int lr = tid >> 3, lkq = tid & 7;
    uint32_t so[4];
#pragma unroll
    for (int q = 0; q < 4; q++)
        so[q] = swz128((lr + q * 32) * 128 + lkq * 16);
    const float* aG = Qp + (long)(i0 + lr) * 1024 + lkq * 4;
    const float* bG = Kp + (long)(j0 + lr) * 1024 + lkq * 4;

    auto issueAB = [&](int kt) {
        const uint32_t sb = base + (uint32_t)(kt % 3) * 32768;
        const long k0 = (long)(kt << 5);
#pragma unroll
        for (int q = 0; q < 4; q++)
            cpasync16(sb + so[q], aG + (long)(q * 32) * 1024 + k0);
#pragma unroll
        for (int q = 0; q < 4; q++)
            cpasync16(sb + 16384 + so[q], bG + (long)(q * 32) * 1024 + k0);
        cpcommit();
    };

    issueAB(0);
    issueAB(1);
    cpwait<1>();
    __syncthreads();

    const int nkt = 8;     // K = 256
    for (int kt = 0; kt < nkt; kt++) {
        const uint32_t stb = base + (uint32_t)(kt % 3) * 32768;
        if (kt + 2 < nkt) issueAB(kt + 2);
        const uint32_t sa = stb, sb = stb + 16384;
#pragma unroll
        for (int s = 0; s < 4; s++) {
            uint32_t af[4][4], bf[4][2];
#pragma unroll
            for (int mt = 0; mt < 4; mt++)
                ldsm4(af[mt], sa + swz128(aoff + mt * 2048 + s * 32));
#pragma unroll
            for (int pp = 0; pp < 2; pp++) {
                uint32_t r[4];
                ldsm4(r, sb + swz128(boff + pp * 2048 + s * 32));
                bf[2 * pp][0] = r[0]; bf[2 * pp][1] = r[1];
                bf[2 * pp + 1][0] = r[2]; bf[2 * pp + 1][1] = r[3];
            }
#pragma unroll
            for (int mt = 0; mt < 4; mt++)
#pragma unroll
                for (int nt = 0; nt < 4; nt++)
                    mma8(acc[mt][nt], af[mt], bf[nt]);
        }
        if (kt + 1 < nkt) {
            if (kt + 2 < nkt) cpwait<1>(); else cpwait<0>();
            __syncthreads();
        }
    }

    // scale + write S tile
#pragma unroll
    for (int mt = 0; mt < 4; mt++) {
        int row = i0 + wm + mt * 16 + (lane >> 2);
#pragma unroll
        for (int nt = 0; nt < 4; nt++) {
            int col = j0 + wn + nt * 8 + (lane & 3) * 2;
            acc[mt][nt][0] *= 0.0625f; acc[mt][nt][1] *= 0.0625f;
            acc[mt][nt][2] *= 0.0625f; acc[mt][nt][3] *= 0.0625f;
            *(float2*)&S[(long)row * Nn + col] =
                make_float2(acc[mt][nt][0], acc[mt][nt][1]);
            *(float2*)&S[(long)(row + 8) * Nn + col] =
                make_float2(acc[mt][nt][2], acc[mt][nt][3]);
        }
    }

    // per-row tile max
    __syncthreads();
#pragma unroll
    for (int mt = 0; mt < 4; mt++) {
#pragma unroll
        for (int h = 0; h < 2; h++) {
            float v = -3e38f;
#pragma unroll
            for (int nt = 0; nt < 4; nt++)
                v = fmaxf(v, fmaxf(acc[mt][nt][2 * h], acc[mt][nt][2 * h + 1]));
            v = fmaxf(v, __shfl_xor_sync(0xffffffffu, v, 1));
            v = fmaxf(v, __shfl_xor_sync(0xffffffffu, v, 2));
            if ((lane & 3) == 0)
                redbuf[(wm + mt * 16 + (lane >> 2) + h * 8) * 4 + (wid >> 1)] = v;
        }
    }
    __syncthreads();
    if (tid < 128)
        mbuf[tid] = fmaxf(fmaxf(redbuf[tid * 4], redbuf[tid * 4 + 1]),
                          fmaxf(redbuf[tid * 4 + 2], redbuf[tid * 4 + 3]));
    __syncthreads();
    // per-row tile sumexp (relative to tile max)
#pragma unroll
    for (int mt = 0; mt < 4; mt++) {
#pragma unroll
        for (int h = 0; h < 2; h++) {
            int row = wm + mt * 16 + (lane >> 2) + h * 8;
            float mn = mbuf[row];
            float s = 0.f;
#pragma unroll
            for (int nt = 0; nt < 4; nt++)
                s += ex2f((acc[mt][nt][2 * h] - mn) * LOG2E)
                   + ex2f((acc[mt][nt][2 * h + 1] - mn) * LOG2E);
            s += __shfl_xor_sync(0xffffffffu, s, 1);
            s += __shfl_xor_sync(0xffffffffu, s, 2);
            if ((lane & 3) == 0)
                redbuf[row * 4 + (wid >> 1)] = s;
        }
    }
    __syncthreads();
    if (tid < 128) {
        long ridx = (long)z * Nn + i0 + tid;
        pm[ridx * 8 + jt] = mbuf[tid];
        pl[ridx * 8 + jt] = redbuf[tid * 4] + redbuf[tid * 4 + 1]
                          + redbuf[tid * 4 + 2] + redbuf[tid * 4 + 3];
    }
}

// combine partials -> off = -(max*LOG2E + log2(sum exp)), fixed jt order
__global__ void combine_stats(const float* __restrict__ pm, const float* __restrict__ pl,
                              float* __restrict__ offv)
{
    long row = (long)blockIdx.x * blockDim.x + threadIdx.x;
    float mv[8];
    float m = -3e38f;
#pragma unroll
    for (int j = 0; j < 8; j++) {
        mv[j] = pm[row * 8 + j];
        m = fmaxf(m, mv[j]);
    }
    float l = 0.f;
#pragma unroll
    for (int j = 0; j < 8; j++)
        l += pl[row * 8 + j] * ex2f((mv[j] - m) * LOG2E);
    offv[row] = -(m * LOG2E + lg2f(l));
}

// PV for all 6 pairs with fused softmax (exp applied in A staging path)
__global__ __launch_bounds__(256)
void gemm_pv(const float* __restrict__ S6, const float* __restrict__ off,
             const float* __restrict__ VT, float* __restrict__ msg)
{
    int z = blockIdx.z, p = z >> 4, b = z & 15, m = p >> 1, j = p & 1;
    int n = j + (j >= m);
    gemm_body<true>(S6 + ((long)p * 16 + b) * NN2,
                    VT + (long)n * BND + (long)b * ND, nullptr,
                    msg + (long)p * BND + (long)b * ND,
                    Dd, Dd, Nn, 1024, 1024,
                    blockIdx.y * 128, blockIdx.x * 128, 1.f, 0, 0,
                    off + ((long)p * 16 + b) * Nn);
}

// ---------------- pre-round x to tf32 ------------------------------------
__global__ void round3_kernel(const float* __restrict__ a, const float* __restrict__ b,
                              const float* __restrict__ c, float* __restrict__ dst)
{
    long i = (long)blockIdx.x * blockDim.x + threadIdx.x;
    long stride = (long)gridDim.x * blockDim.x;
    for (; i < BND; i += stride) {
        dst[i]            = rna_f(a[i]);
        dst[BND + i]      = rna_f(b[i]);
        dst[2L * BND + i] = rna_f(c[i]);
    }
}

// ---------------- transpose (dst[C][R] = src[R][C]), tf32-rounded ---------
__global__ void transpose_kernel(const float* __restrict__ src, float* __restrict__ dst,
                                 int R, int C, int srcPitch, long sS, long sD)
{
    __shared__ float t[32][33];
    src += (long)blockIdx.z * sS;
    dst += (long)blockIdx.z * sD;
    int c = blockIdx.x * 32 + threadIdx.x;
    int r0 = blockIdx.y * 32;
    for (int j = threadIdx.y; j < 32; j += 8)
        t[j][threadIdx.x] = src[(long)(r0 + j) * srcPitch + c];
    __syncthreads();
    int rr = blockIdx.y * 32 + threadIdx.x;
    int cc0 = blockIdx.x * 32;
    for (int j = threadIdx.y; j < 32; j += 8)
        dst[(long)(cc0 + j) * R + rr] = rna_f(t[threadIdx.x][j]);
}

// 5 weight transposes in one launch (z selects matrix)
__global__ void transpose_w5(const float* w0, const float* w1, const float* w2,
                             const float* w3, const float* w4, float* __restrict__ dst)
{
    __shared__ float t[32][33];
    const float* src = (blockIdx.z == 0) ? w0 : (blockIdx.z == 1) ? w1 :
                       (blockIdx.z == 2) ? w2 : (blockIdx.z == 3) ? w3 : w4;
    dst += (long)blockIdx.z * Dd * Dd;
    int c = blockIdx.x * 32 + threadIdx.x;
    int r0 = blockIdx.y * 32;
    for (int j = threadIdx.y; j < 32; j += 8)
        t[j][threadIdx.x] = src[(long)(r0 + j) * Dd + c];
    __syncthreads();
    int rr = blockIdx.y * 32 + threadIdx.x;
    int cc0 = blockIdx.x * 32;
    for (int j = threadIdx.y; j < 32; j += 8)
        dst[(long)(cc0 + j) * Dd + rr] = rna_f(t[threadIdx.x][j]);
}

// packed bias [bQ|bK|bV|bO]
__global__ void pack_bias(const float* q, const float* k, const float* v,
                          const float* o, float* __restrict__ pb)
{
    int i = blockIdx.x * 256 + threadIdx.x;
    const float* s = (i < 256) ? q : (i < 512) ? k : (i < 768) ? v : o;
    pb[i] = s[i & 255];
}

// ---------------- fast deterministic CSR build ----------------------------
__global__ void zero_cnt_kernel(int* ncnt, int* ecnt)
{
    int i = blockIdx.x * blockDim.x + threadIdx.x;
    if (i < 3 * Nn) ncnt[i] = 0;
    if (i < 3 * Mm) ecnt[i] = 0;
}

__global__ void csr_count_kernel(const int* __restrict__ i0, const int* __restrict__ i1,
                                 const int* __restrict__ i2, int cnt_stride, int edge_off,
                                 int* __restrict__ cnt)
{
    const int* idx = (blockIdx.y == 0) ? i0 : (blockIdx.y == 1) ? i1 : i2;
    int c = blockIdx.x * blockDim.x + threadIdx.x;
    atomicAdd(&cnt[blockIdx.y * cnt_stride + idx[edge_off + c]], 1);
}

__global__ void csr_scan_kernel(const int* __restrict__ cnt, int* __restrict__ off, int nseg)
{
    __shared__ int buf[1024];
    int tid = threadIdx.x;
    int v = (tid < nseg) ? cnt[blockIdx.x * nseg + tid] : 0;
    buf[tid] = v;
    __syncthreads();
    for (int o = 1; o < nseg; o <<= 1) {
        int t = (tid >= o) ? buf[tid - o] : 0;
        __syncthreads();
        buf[tid] += t;
        __syncthreads();
    }
    if (tid < nseg) off[blockIdx.x * nseg + tid] = buf[tid] - v;
}

__global__ void csr_fill_kernel(const int* __restrict__ i0, const int* __restrict__ i1,
                                const int* __restrict__ i2, int nseg, int edge_off,
                                const int* __restrict__ off, int* __restrict__ list)
{
    __shared__ int sidx[Cc];
    const int* idx = (blockIdx.y == 0) ? i0 : (blockIdx.y == 1) ? i1 : i2;
    int tid = threadIdx.x;
    for (int i = tid; i < Cc; i += blockDim.x) sidx[i] = idx[edge_off + i];
    __syncthreads();

    int w = tid >> 5, lane = tid & 31;
    int s = blockIdx.x * 8 + w;
    if (s >= nseg) return;
    int p = off[blockIdx.y * nseg + s];
    int* lst = list + blockIdx.y * Cc;
    for (int c0 = 0; c0 < Cc; c0 += 32) {
        int c = c0 + lane;
        bool m = (sidx[c] == s);
        unsigned bal = __ballot_sync(0xffffffffu, m);
        if (m) lst[p + __popc(bal & ((1u << lane) - 1u))] = c;
        p += __popc(bal);
    }
}

// ---------------- sparse stage kernels (z = modality) ---------------------
__global__ void edge_sum_kernel(const float* __restrict__ xp,
                                const int* __restrict__ h0, const int* __restrict__ h1,
                                const int* __restrict__ h2,
                                const int* __restrict__ ecnt, const int* __restrict__ eoff,
                                const int* __restrict__ elist, float* __restrict__ es)
{
    int mmod = blockIdx.z;
    const int* hidx = (mmod == 0) ? h0 : (mmod == 1) ? h1 : h2;
    xp += (long)mmod * BND;
    es += (long)mmod * Mm * Bdim * Dd;
    ecnt += mmod * Mm; eoff += mmod * Mm; elist += mmod * Cc;

    int e = blockIdx.x, b = blockIdx.y, d = threadIdx.x;
    int cnt = ecnt[e], off = eoff[e];
    float s = 0.f;
    for (int i = 0; i < cnt; i++) {
        int c = elist[off + i];
        int node = hidx[c];
        s += xp[((long)b * Nn + node) * Dd + d];
    }
    es[((long)e * Bdim + b) * Dd + d] = s;
}

// proj: p1[mod][row] = dot(xp[row,:], att[0:D]); p2 for es rows
__global__ void proj_kernel(const float* __restrict__ xp, const float* __restrict__ es,
                            const float* __restrict__ att,
                            float* __restrict__ p1, float* __restrict__ p2)
{
    int mmod = blockIdx.y;
    int row = blockIdx.x * 8 + (threadIdx.x >> 5);
    int lane = threadIdx.x & 31;
    const float* src;
    const float* a;
    if (row < Bdim * Nn) {
        src = xp + (long)mmod * BND + (long)row * Dd;
        a = att;
    } else {
        src = es + (long)mmod * Mm * Bdim * Dd + (long)(row - Bdim * Nn) * Dd;
        a = att + Dd;
    }
    float s = 0.f;
#pragma unroll
    for (int i = 0; i < Dd / 32; i++) {
        int d = lane + 32 * i;
        s += src[d] * a[d];
    }
#pragma unroll
    for (int o = 16; o; o >>= 1) s += __shfl_xor_sync(0xffffffffu, s, o);
    if (lane == 0) {
        if (row < Bdim * Nn) p1[mmod * Bdim * Nn + row] = s;
        else                 p2[mmod * Mm * Bdim + row - Bdim * Nn] = s;
    }
}

__global__ void logits_gather(const int* __restrict__ h0, const int* __restrict__ h1,
                              const int* __restrict__ h2,
                              const float* __restrict__ p1, const float* __restrict__ p2,
                              float* __restrict__ e_out)
{
    int mmod = blockIdx.y;
    const int* hidx = (mmod == 0) ? h0 : (mmod == 1) ? h1 : h2;
    int i = blockIdx.x * blockDim.x + threadIdx.x;
    int c = i >> 4, b = i & 15;
    float v = p1[mmod * Bdim * Nn + b * Nn + hidx[c]]
            + p2[mmod * Mm * Bdim + hidx[Cc + c] * Bdim + b];
    e_out[(long)mmod * Cc * Bdim + i] = (v >= 0.f) ? v : NEG_SLOPE * v;
}

__global__ void node_softmax(float* __restrict__ e, const int* __restrict__ ncnt,
                             const int* __restrict__ noff, const int* __restrict__ nlist)
{
    int mmod = blockIdx.y;
    e += (long)mmod * Cc * Bdim;
    ncnt += mmod * Nn; noff += mmod * Nn; nlist += mmod * Cc;

    int n = blockIdx.x, b = threadIdx.x;
    if (b >= Bdim) return;
    int cnt = ncnt[n];
    if (!cnt) return;
    int off = noff[n];
    float mx = -1e30f;
    for (int i = 0; i < cnt; i++) {
        int c = nlist[off + i];
        mx = fmaxf(mx, e[c * Bdim + b]);
    }
    float sum = 0.f;
    for (int i = 0; i < cnt; i++) {
        int c = nlist[off + i];
        float v = expf(e[c * Bdim + b] - mx);
        e[c * Bdim + b] = v;
        sum += v;
    }
    float inv = 1.f / (sum + 1e-16f);
    for (int i = 0; i < cnt; i++) {
        int c = nlist[off + i];
        e[c * Bdim + b] *= inv;
    }
}

__global__ void xedge_kernel(const float* __restrict__ xp, const float* __restrict__ alpha,
                             const int* __restrict__ h0, const int* __restrict__ h1,
                             const int* __restrict__ h2,
                             const int* __restrict__ ecnt, const int* __restrict__ eoff,
                             const int* __restrict__ elist, float* __restrict__ xe)
{
    int mmod = blockIdx.z;
    const int* hidx = (mmod == 0) ? h0 : (mmod == 1) ? h1 : h2;
    xp += (long)mmod * BND;
    alpha += (long)mmod * Cc * Bdim;
    xe += (long)mmod * Mm * Bdim * Dd;
    ecnt += mmod * Mm; eoff += mmod * Mm; elist += mmod * Cc;

    int e = blockIdx.x, b = blockIdx.y, d = threadIdx.x;
    int cnt = ecnt[e];
    float s = 0.f;
    if (cnt) {
        int off = eoff[e];
        for (int i = 0; i < cnt; i++) {
            int c = elist[off + i];
            int node = hidx[c];
            s += alpha[c * Bdim + b] * xp[((long)b * Nn + node) * Dd + d];
        }
        s /= (float)cnt;
    }
    xe[((long)e * Bdim + b) * Dd + d] = s;
}

__global__ void xnode_kernel(const float* __restrict__ xe, const float* __restrict__ alpha,
                             const int* __restrict__ h0, const int* __restrict__ h1,
                             const int* __restrict__ h2,
                             const int* __restrict__ ncnt, const int* __restrict__ noff,
                             const int* __restrict__ nlist, float* __restrict__ h)
{
    int mmod = blockIdx.z;
    const int* hidx = (mmod == 0) ? h0 : (mmod == 1) ? h1 : h2;
    xe += (long)mmod * Mm * Bdim * Dd;
    alpha += (long)mmod * Cc * Bdim;
    h += (long)mmod * BND;
    ncnt += mmod * Nn; noff += mmod * Nn; nlist += mmod * Cc;

    int n = blockIdx.x, b = blockIdx.y, d = threadIdx.x;
    int cnt = ncnt[n];
    float s = 0.f;
    if (cnt) {
        int off = noff[n];
        for (int i = 0; i < cnt; i++) {
            int c = nlist[off + i];
            int eidx = hidx[Cc + c];
            s += alpha[c * Bdim + b] * xe[((long)eidx * Bdim + b) * Dd + d];
        }
        s /= (float)cnt;
    }
    h[((long)b * Nn + n) * Dd + d] = rna_f(s);
}

// ---------------- out = relu(base(pack col 768+) + msg0 + msg1) -----------
__global__ void relu_final(float* __restrict__ out, const float* __restrict__ pack,
                           const float* __restrict__ msg)
{
    long i = (long)blockIdx.x * blockDim.x + threadIdx.x;
    long stride = (long)gridDim.x * blockDim.x;
    for (; i < BND; i += stride) {
        long r = i >> 8;
        int d = (int)(i & 255);
#pragma unroll
        for (int m = 0; m < 3; m++) {
            float v = pack[((long)m * (Bdim * Nn) + r) * 1024 + 768 + d]
                    + msg[(long)(2 * m) * BND + i]
                    + msg[(long)(2 * m + 1) * BND + i];
            out[(long)m * BND + i] = fmaxf(v, 0.f);
        }
    }
}

// ---------------- launcher -------------------------------------------------
extern "C" void kernel_launch(void* const* d_in, const int* in_sizes, int n_in,
                              void* d_out, int out_size)
{
    const float* x[3]    = {(const float*)d_in[0], (const float*)d_in[1], (const float*)d_in[2]};
    const int*   hidx[3] = {(const int*)d_in[3], (const int*)d_in[4], (const int*)d_in[5]};
    const float* W_hg = (const float*)d_in[6];
    const float* att  = (const float*)d_in[7];
    const float* WQ = (const float*)d_in[8];
    const float* bQ = (const float*)d_in[9];
    const float* WK = (const float*)d_in[10];
    const float* bK = (const float*)d_in[11];
    const float* WV = (const float*)d_in[12];
    const float* bV = (const float*)d_in[13];
    const float* WO = (const float*)d_in[14];
    const float* bO = (const float*)d_in[15];
    float* out = (float*)d_out;

    static int smem_set = 0;
    if (!smem_set) {
        cudaFuncSetAttribute(gemm_lin, cudaFuncAttributeMaxDynamicSharedMemorySize, GEMM_SMEM);
        cudaFuncSetAttribute(gemm_qk_part, cudaFuncAttributeMaxDynamicSharedMemorySize, GEMM_SMEM);
        cudaFuncSetAttribute(gemm_pv,  cudaFuncAttributeMaxDynamicSharedMemorySize, GEMM_SMEM);
        smem_set = 1;
    }

    float *xp, *h, *Q, *pack, *pb, *VT, *WT, *S6, *offb, *pm, *pl, *msg;
    float *es, *xe, *ealpha, *p1, *p2;
    int *ncnt, *noff, *nlist, *ecnt, *eoff, *elist;
    cudaGetSymbolAddress((void**)&xp, g_xp);
    cudaGetSymbolAddress((void**)&h,  g_h);
    cudaGetSymbolAddress((void**)&Q,  g_Q);
    cudaGetSymbolAddress((void**)&pack, g_pack);
    cudaGetSymbolAddress((void**)&pb, g_pb);
    cudaGetSymbolAddress((void**)&VT, g_VT);
    cudaGetSymbolAddress((void**)&WT, g_WT);
    cudaGetSymbolAddress((void**)&S6, g_S6);
    cudaGetSymbolAddress((void**)&offb, g_off);
    cudaGetSymbolAddress((void**)&pm, g_pm);
    cudaGetSymbolAddress((void**)&pl, g_pl);
    cudaGetSymbolAddress((void**)&msg, g_msg);
    cudaGetSymbolAddress((void**)&es, g_es);
    cudaGetSymbolAddress((void**)&xe, g_xe);
    cudaGetSymbolAddress((void**)&ealpha, g_e);
    cudaGetSymbolAddress((void**)&p1, g_p1);
    cudaGetSymbolAddress((void**)&p2, g_p2);
    cudaGetSymbolAddress((void**)&ncnt, g_ncnt);
    cudaGetSymbolAddress((void**)&noff, g_noff);
    cudaGetSymbolAddress((void**)&nlist, g_nlist);
    cudaGetSymbolAddress((void**)&ecnt, g_ecnt);
    cudaGetSymbolAddress((void**)&eoff, g_eoff);
    cudaGetSymbolAddress((void**)&elist, g_elist);

    const int DD = Dd * Dd;

    // 0) weight transposes (tf32-rounded) + pre-round x + packed bias
    transpose_w5<<<dim3(8, 8, 5), dim3(32, 8)>>>(W_hg, WQ, WK, WV, WO, WT);
    round3_kernel<<<4096, 256>>>(x[0], x[1], x[2], Q);
    pack_bias<<<4, 256>>>(bQ, bK, bV, bO, pb);

    // 1) xp = x @ W_hg, all 3 modalities
    gemm_lin<<<dim3(2, 128, 3), 256, GEMM_SMEM>>>(Q, WT, nullptr, xp,
                                                  Dd, Dd, Dd, Dd, Dd,
                                                  BND, 0, BND, 1.f, 0, 0);

    // 2) CSR build (parallel, deterministic: lists sorted by c)
    zero_cnt_kernel<<<4, 1024>>>(ncnt, ecnt);
    csr_count_kernel<<<dim3(Cc / 256, 3), 256>>>(hidx[0], hidx[1], hidx[2], Nn, 0,  ncnt);
    csr_count_kernel<<<dim3(Cc / 256, 3), 256>>>(hidx[0], hidx[1], hidx[2], Mm, Cc, ecnt);
    csr_scan_kernel<<<3, 1024>>>(ncnt, noff, Nn);
    csr_scan_kernel<<<3, 1024>>>(ecnt, eoff, Mm);
    csr_fill_kernel<<<dim3(Nn / 8, 3), 256>>>(hidx[0], hidx[1], hidx[2], Nn, 0,  noff, nlist);
    csr_fill_kernel<<<dim3(Mm / 8, 3), 256>>>(hidx[0], hidx[1], hidx[2], Mm, Cc, eoff, elist);

    // 3-7) sparse hypergraph pipeline
    edge_sum_kernel<<<dim3(Mm, Bdim, 3), Dd>>>(xp, hidx[0], hidx[1], hidx[2],
                                               ecnt, eoff, elist, es);
    proj_kernel<<<dim3((Bdim * Nn + Mm * Bdim) / 8, 3), 256>>>(xp, es, att, p1, p2);
    logits_gather<<<dim3(Cc * Bdim / 256, 3), 256>>>(hidx[0], hidx[1], hidx[2],
                                                     p1, p2, ealpha);
    node_softmax<<<dim3(Nn, 3), 32>>>(ealpha, ncnt, noff, nlist);
    xedge_kernel<<<dim3(Mm, Bdim, 3), Dd>>>(xp, ealpha, hidx[0], hidx[1], hidx[2],
                                            ecnt, eoff, elist, xe);
    xnode_kernel<<<dim3(Nn, Bdim, 3), Dd>>>(xe, ealpha, hidx[0], hidx[1], hidx[2],
                                            ncnt, noff, nlist, h);

    // 8) fused Q|K|V|O projections: [49152,256] @ [256,1024] -> packed
    gemm_lin<<<dim3(8, 384, 1), 256, GEMM_SMEM>>>(h, WT + DD, pb, pack,
                                                  1024, 1024, Dd, Dd, Dd,
                                                  0, 0, 0, 1.f, 0, 1);

    // 8b) VT[z][d][n] from pack V columns (pitch 1024), tf32-rounded
    transpose_kernel<<<dim3(Dd / 32, Nn / 32, 48), dim3(32, 8)>>>(
        pack + 512, VT, Nn, Dd, 1024, (long)Nn * 1024, ND);

    // 9) cross-modal attention: tiled QK^T with stats partials -> combine ->
    //    PV with fused softmax
    gemm_qk_part<<<dim3(8, 8, 96), 256, GEMM_SMEM>>>(pack, S6, pm, pl);
    combine_stats<<<6 * Bdim * Nn / 256, 256>>>(pm, pl, offb);
    gemm_pv<<<dim3(2, 8, 96), 256, GEMM_SMEM>>>(S6, offb, VT, msg);

    // 10) final combine + relu
    relu_final<<<4096, 256>>>(out, pack, msg);
}